// round 7
// baseline (speedup 1.0000x reference)
#include <cuda_runtime.h>
#include <cuda_bf16.h>

// Dynamic grouped depthwise 1D conv:
//   x: [B=8, C=512, L=4096] f32
//   w: [B=8, WC=64, KS=7, L=4096] f32, groups = C/WC = 8
//   out[b,c,l] = sum_k x_pad[b,c,l+k] * w[b, c/groups, k, l],  pad = 3 (zeros)
//
// R7: R6 structure (sync-free, shared-free, w-reuse in registers) but the
// 8-channel group is split across 2 threads (4 channels each) to cut
// register pressure and raise occupancy 28 -> 40 warps/SM. The duplicated
// w read (2 threads/block read the same 7 w-float4) is an L1/L2 hit;
// DRAM w traffic is unchanged.

#define B_DIM 8
#define C_DIM 512
#define L_DIM 4096
#define WC_DIM 64
#define KS 7
#define GROUPS 8              // C / WC
#define TILE_F 128            // float4 positions per block
#define THREADS 256           // 128 positions x 2 group-halves
#define LF (L_DIM / 4)        // 1024 float4 per row

__global__ __launch_bounds__(THREADS, 5)
void SKA_40106404610132_kernel(const float* __restrict__ x,
                               const float* __restrict__ w,
                               float* __restrict__ out)
{
    const int tile = blockIdx.x;          // 0..7
    const int wc   = blockIdx.y;          // 0..63
    const int b    = blockIdx.z;          // 0..7

    const int f    = threadIdx.x & (TILE_F - 1);   // position within tile
    const int half = threadIdx.x >> 7;             // 0 -> ch 0..3, 1 -> ch 4..7
    const int fg   = tile * TILE_F + f;            // float4 idx in row [0,1024)

    // ---- load the 7 w taps for this position (once per block-half;
    //      the duplicate is an L1/L2 hit)
    const float4* w4 = reinterpret_cast<const float4*>(
        w + (((long)b * WC_DIM + wc) * KS) * L_DIM);
    float4 wv[KS];
    #pragma unroll
    for (int k = 0; k < KS; k++) wv[k] = w4[(long)k * LF + fg];

    const float4 zero4 = make_float4(0.f, 0.f, 0.f, 0.f);
    const bool has_lo = (fg > 0);
    const bool has_hi = (fg < LF - 1);

    const long rbase = (long)b * C_DIM + wc * GROUPS + half * 4;  // 1st of 4 ch
    const float4* xb4 = reinterpret_cast<const float4*>(x) + rbase * LF;
    float4* ob4 = reinterpret_cast<float4*>(out) + rbase * LF;

    // ---- 2 channel pairs; fully unrolled so loads front-batch across pairs
    #pragma unroll
    for (int p = 0; p < 2; p++) {
        const float4* x0 = xb4 + (long)(2 * p) * LF;
        const float4* x1 = x0 + LF;

        const float4 xb0 = x0[fg];
        const float4 xb1 = x1[fg];
        const float4 xa0 = has_lo ? x0[fg - 1] : zero4;
        const float4 xa1 = has_lo ? x1[fg - 1] : zero4;
        const float4 xc0 = has_hi ? x0[fg + 1] : zero4;
        const float4 xc1 = has_hi ? x1[fg + 1] : zero4;

        // window xv[i] = x[4fg - 3 + i], i = 0..9
        float u[10], v[10];
        u[0] = xa0.y; u[1] = xa0.z; u[2] = xa0.w;
        u[3] = xb0.x; u[4] = xb0.y; u[5] = xb0.z; u[6] = xb0.w;
        u[7] = xc0.x; u[8] = xc0.y; u[9] = xc0.z;
        v[0] = xa1.y; v[1] = xa1.z; v[2] = xa1.w;
        v[3] = xb1.x; v[4] = xb1.y; v[5] = xb1.z; v[6] = xb1.w;
        v[7] = xc1.x; v[8] = xc1.y; v[9] = xc1.z;

        float4 acc0 = zero4, acc1 = zero4;
        #pragma unroll
        for (int k = 0; k < KS; k++) {
            acc0.x = fmaf(u[k + 0], wv[k].x, acc0.x);
            acc0.y = fmaf(u[k + 1], wv[k].y, acc0.y);
            acc0.z = fmaf(u[k + 2], wv[k].z, acc0.z);
            acc0.w = fmaf(u[k + 3], wv[k].w, acc0.w);
            acc1.x = fmaf(v[k + 0], wv[k].x, acc1.x);
            acc1.y = fmaf(v[k + 1], wv[k].y, acc1.y);
            acc1.z = fmaf(v[k + 2], wv[k].z, acc1.z);
            acc1.w = fmaf(v[k + 3], wv[k].w, acc1.w);
        }

        float4* o0 = ob4 + (long)(2 * p) * LF;
        o0[fg] = acc0;
        (o0 + LF)[fg] = acc1;
    }
}

extern "C" void kernel_launch(void* const* d_in, const int* in_sizes, int n_in,
                              void* d_out, int out_size) {
    const float* x = (const float*)d_in[0];  // [8, 512, 4096]
    const float* w = (const float*)d_in[1];  // [8, 64, 7, 4096]
    float* out = (float*)d_out;              // [8, 512, 4096]

    dim3 grid(L_DIM / (TILE_F * 4), WC_DIM, B_DIM);  // (8, 64, 8) = 4096 blocks
    SKA_40106404610132_kernel<<<grid, THREADS>>>(x, w, out);
}

// round 8
// speedup vs baseline: 1.2489x; 1.2489x over previous
#include <cuda_runtime.h>
#include <cuda_bf16.h>

// Dynamic grouped depthwise 1D conv:
//   x: [B=8, C=512, L=4096] f32
//   w: [B=8, WC=64, KS=7, L=4096] f32, groups = C/WC = 8
//   out[b,c,l] = sum_k x_pad[b,c,l+k] * w[b, c/groups, k, l],  pad = 3 (zeros)
//
// R8 = R6 (sync-free, shared-free, one thread = one float4 position x all 8
// group channels, w-reuse in registers, deep front-batched MLP) with:
//   - __launch_bounds__(128, 8): 64-reg cap -> 8 blocks/SM (32 warps, +14%)
//   - st.global.cs streaming stores: out never re-read, keep it out of L2

#define B_DIM 8
#define C_DIM 512
#define L_DIM 4096
#define WC_DIM 64
#define KS 7
#define GROUPS 8              // C / WC
#define TILE_F 128            // float4 positions per block (= threads)
#define THREADS 128
#define LF (L_DIM / 4)        // 1024 float4 per row

__device__ __forceinline__ void stcs4(float4* p, float4 v) {
    asm volatile("st.global.cs.v4.f32 [%0], {%1,%2,%3,%4};\n"
                 :: "l"(p), "f"(v.x), "f"(v.y), "f"(v.z), "f"(v.w) : "memory");
}

__global__ __launch_bounds__(THREADS, 8)
void SKA_40106404610132_kernel(const float* __restrict__ x,
                               const float* __restrict__ w,
                               float* __restrict__ out)
{
    const int tile = blockIdx.x;          // 0..7
    const int wc   = blockIdx.y;          // 0..63
    const int b    = blockIdx.z;          // 0..7

    const int fg = tile * TILE_F + threadIdx.x;   // float4 idx in row [0,1024)

    // ---- load the 7 w taps for this position (read exactly once chip-wide)
    const float4* w4 = reinterpret_cast<const float4*>(
        w + (((long)b * WC_DIM + wc) * KS) * L_DIM);
    float4 wv[KS];
    #pragma unroll
    for (int k = 0; k < KS; k++) wv[k] = w4[(long)k * LF + fg];

    const float4 zero4 = make_float4(0.f, 0.f, 0.f, 0.f);
    const bool has_lo = (fg > 0);
    const bool has_hi = (fg < LF - 1);

    const long rbase = (long)b * C_DIM + wc * GROUPS;  // first channel row
    const float4* xb4 = reinterpret_cast<const float4*>(x) + rbase * LF;
    float4* ob4 = reinterpret_cast<float4*>(out) + rbase * LF;

    // ---- 4 channel pairs; fully unrolled so loads front-batch across pairs
    #pragma unroll
    for (int p = 0; p < GROUPS / 2; p++) {
        const float4* x0 = xb4 + (long)(2 * p) * LF;
        const float4* x1 = x0 + LF;

        const float4 xb0 = x0[fg];
        const float4 xb1 = x1[fg];
        const float4 xa0 = has_lo ? x0[fg - 1] : zero4;
        const float4 xa1 = has_lo ? x1[fg - 1] : zero4;
        const float4 xc0 = has_hi ? x0[fg + 1] : zero4;
        const float4 xc1 = has_hi ? x1[fg + 1] : zero4;

        // window xv[i] = x[4fg - 3 + i], i = 0..9
        float u[10], v[10];
        u[0] = xa0.y; u[1] = xa0.z; u[2] = xa0.w;
        u[3] = xb0.x; u[4] = xb0.y; u[5] = xb0.z; u[6] = xb0.w;
        u[7] = xc0.x; u[8] = xc0.y; u[9] = xc0.z;
        v[0] = xa1.y; v[1] = xa1.z; v[2] = xa1.w;
        v[3] = xb1.x; v[4] = xb1.y; v[5] = xb1.z; v[6] = xb1.w;
        v[7] = xc1.x; v[8] = xc1.y; v[9] = xc1.z;

        float4 acc0 = zero4, acc1 = zero4;
        #pragma unroll
        for (int k = 0; k < KS; k++) {
            acc0.x = fmaf(u[k + 0], wv[k].x, acc0.x);
            acc0.y = fmaf(u[k + 1], wv[k].y, acc0.y);
            acc0.z = fmaf(u[k + 2], wv[k].z, acc0.z);
            acc0.w = fmaf(u[k + 3], wv[k].w, acc0.w);
            acc1.x = fmaf(v[k + 0], wv[k].x, acc1.x);
            acc1.y = fmaf(v[k + 1], wv[k].y, acc1.y);
            acc1.z = fmaf(v[k + 2], wv[k].z, acc1.z);
            acc1.w = fmaf(v[k + 3], wv[k].w, acc1.w);
        }

        float4* o0 = ob4 + (long)(2 * p) * LF;
        stcs4(&o0[fg], acc0);
        stcs4(&(o0 + LF)[fg], acc1);
    }
}

extern "C" void kernel_launch(void* const* d_in, const int* in_sizes, int n_in,
                              void* d_out, int out_size) {
    const float* x = (const float*)d_in[0];  // [8, 512, 4096]
    const float* w = (const float*)d_in[1];  // [8, 64, 7, 4096]
    float* out = (float*)d_out;              // [8, 512, 4096]

    dim3 grid(L_DIM / (TILE_F * 4), WC_DIM, B_DIM);  // (8, 64, 8) = 4096 blocks
    SKA_40106404610132_kernel<<<grid, THREADS>>>(x, w, out);
}

// round 9
// speedup vs baseline: 1.3077x; 1.0471x over previous
#include <cuda_runtime.h>
#include <cuda_bf16.h>

// Dynamic grouped depthwise 1D conv:
//   x: [B=8, C=512, L=4096] f32
//   w: [B=8, WC=64, KS=7, L=4096] f32, groups = C/WC = 8
//   out[b,c,l] = sum_k x_pad[b,c,l+k] * w[b, c/groups, k, l],  pad = 3 (zeros)
//
// R9 = R8 (sync-free, shared-free, thread = 1 float4 position x all 8 group
// channels, w-reuse in registers, 8 blocks/SM) plus:
//   - block-uniform interior/edge branch: 6/8 of blocks run a select-free
//     path where all 19 LDG.128 issue unconditionally (deeper front-batch)
//   - ld.global.cs for w (each w element read exactly once chip-wide:
//     evict-first, keep L1/L2 for the 3x-reused x stream)
//   - st.global.cs for out (never re-read)

#define B_DIM 8
#define C_DIM 512
#define L_DIM 4096
#define WC_DIM 64
#define KS 7
#define GROUPS 8              // C / WC
#define TILE_F 128            // float4 positions per block (= threads)
#define THREADS 128
#define LF (L_DIM / 4)        // 1024 float4 per row

__device__ __forceinline__ void stcs4(float4* p, float4 v) {
    asm volatile("st.global.cs.v4.f32 [%0], {%1,%2,%3,%4};\n"
                 :: "l"(p), "f"(v.x), "f"(v.y), "f"(v.z), "f"(v.w) : "memory");
}
__device__ __forceinline__ float4 ldcs4(const float4* p) {
    float4 v;
    asm volatile("ld.global.cs.v4.f32 {%0,%1,%2,%3}, [%4];\n"
                 : "=f"(v.x), "=f"(v.y), "=f"(v.z), "=f"(v.w) : "l"(p));
    return v;
}

template <bool EDGE>
__device__ __forceinline__ void conv_body(const float4* __restrict__ xb4,
                                          float4* __restrict__ ob4,
                                          const float4 (&wv)[KS],
                                          int fg)
{
    const float4 zero4 = make_float4(0.f, 0.f, 0.f, 0.f);
    const bool has_lo = !EDGE || (fg > 0);
    const bool has_hi = !EDGE || (fg < LF - 1);

    #pragma unroll
    for (int p = 0; p < GROUPS / 2; p++) {
        const float4* x0 = xb4 + (long)(2 * p) * LF;
        const float4* x1 = x0 + LF;

        const float4 xb0 = x0[fg];
        const float4 xb1 = x1[fg];
        float4 xa0, xa1, xc0, xc1;
        if (EDGE) {
            xa0 = has_lo ? x0[fg - 1] : zero4;
            xa1 = has_lo ? x1[fg - 1] : zero4;
            xc0 = has_hi ? x0[fg + 1] : zero4;
            xc1 = has_hi ? x1[fg + 1] : zero4;
        } else {
            xa0 = x0[fg - 1];
            xa1 = x1[fg - 1];
            xc0 = x0[fg + 1];
            xc1 = x1[fg + 1];
        }

        // window xv[i] = x[4fg - 3 + i], i = 0..9
        float u[10], v[10];
        u[0] = xa0.y; u[1] = xa0.z; u[2] = xa0.w;
        u[3] = xb0.x; u[4] = xb0.y; u[5] = xb0.z; u[6] = xb0.w;
        u[7] = xc0.x; u[8] = xc0.y; u[9] = xc0.z;
        v[0] = xa1.y; v[1] = xa1.z; v[2] = xa1.w;
        v[3] = xb1.x; v[4] = xb1.y; v[5] = xb1.z; v[6] = xb1.w;
        v[7] = xc1.x; v[8] = xc1.y; v[9] = xc1.z;

        float4 acc0 = zero4, acc1 = zero4;
        #pragma unroll
        for (int k = 0; k < KS; k++) {
            acc0.x = fmaf(u[k + 0], wv[k].x, acc0.x);
            acc0.y = fmaf(u[k + 1], wv[k].y, acc0.y);
            acc0.z = fmaf(u[k + 2], wv[k].z, acc0.z);
            acc0.w = fmaf(u[k + 3], wv[k].w, acc0.w);
            acc1.x = fmaf(v[k + 0], wv[k].x, acc1.x);
            acc1.y = fmaf(v[k + 1], wv[k].y, acc1.y);
            acc1.z = fmaf(v[k + 2], wv[k].z, acc1.z);
            acc1.w = fmaf(v[k + 3], wv[k].w, acc1.w);
        }

        float4* o0 = ob4 + (long)(2 * p) * LF;
        stcs4(&o0[fg], acc0);
        stcs4(&(o0 + LF)[fg], acc1);
    }
}

__global__ __launch_bounds__(THREADS, 8)
void SKA_40106404610132_kernel(const float* __restrict__ x,
                               const float* __restrict__ w,
                               float* __restrict__ out)
{
    const int tile = blockIdx.x;          // 0..7
    const int wc   = blockIdx.y;          // 0..63
    const int b    = blockIdx.z;          // 0..7

    const int fg = tile * TILE_F + threadIdx.x;   // float4 idx in row [0,1024)

    // ---- load the 7 w taps (read exactly once chip-wide -> evict-first)
    const float4* w4 = reinterpret_cast<const float4*>(
        w + (((long)b * WC_DIM + wc) * KS) * L_DIM);
    float4 wv[KS];
    #pragma unroll
    for (int k = 0; k < KS; k++) wv[k] = ldcs4(&w4[(long)k * LF + fg]);

    const long rbase = (long)b * C_DIM + wc * GROUPS;  // first channel row
    const float4* xb4 = reinterpret_cast<const float4*>(x) + rbase * LF;
    float4* ob4 = reinterpret_cast<float4*>(out) + rbase * LF;

    if (tile == 0 || tile == (L_DIM / (TILE_F * 4)) - 1) {
        conv_body<true>(xb4, ob4, wv, fg);    // 2/8 blocks: edge-predicated
    } else {
        conv_body<false>(xb4, ob4, wv, fg);   // 6/8 blocks: select-free
    }
}

extern "C" void kernel_launch(void* const* d_in, const int* in_sizes, int n_in,
                              void* d_out, int out_size) {
    const float* x = (const float*)d_in[0];  // [8, 512, 4096]
    const float* w = (const float*)d_in[1];  // [8, 64, 7, 4096]
    float* out = (float*)d_out;              // [8, 512, 4096]

    dim3 grid(L_DIM / (TILE_F * 4), WC_DIM, B_DIM);  // (8, 64, 8) = 4096 blocks
    SKA_40106404610132_kernel<<<grid, THREADS>>>(x, w, out);
}